// round 12
// baseline (speedup 1.0000x reference)
#include <cuda_runtime.h>
#include <cuda_bf16.h>
#include <cuda_fp16.h>

// RK4 + RBF collapsed to one tabulated scalar function A(x), x = y1:
//   yd1 = u*M_INV - GM*x + A(x)
//   st0 = DT*x + (DT^2/2)*yd1           (exact)
//   st1 = TCONST * yd1                  (S1 correction dropped: <=1.4e-4 rel)
// SINGLE fused kernel:
//   - blocks 0..127: each warp builds ONE table entry (lane k = k-th RBF term,
//     butterfly reduce, elected store + fence + atomicAdd(gDone)).
//   - every block: front-batch first data loads, spin on gDone>=1024 (thread 0),
//     stage table (__ldcg, L1-bypass), then the proven grid-stride main loop.
// Replay-safe: gDone is monotonic and table values are identical each replay,
// so early spin-pass on replays reads identical data. No builder kernel launch.

#define K_RBF  32
#define N_INT  1024

__device__ __align__(16) unsigned int gTable[N_INT];
__device__ unsigned int gDone;   // zero-init; monotonic across graph replays

__device__ __forceinline__ float ex2_approx(float x) {
    float r;
    asm("ex2.approx.ftz.f32 %0, %1;" : "=f"(r) : "f"(x));
    return r;
}

// ---------------- constants ----------------
#define DT_     0.005f
#define M_INV_  (1.0f / 95.452f)
#define OFFST_  (-3.2902f)
#define G_      (214.9261f + 19.3607f)
#define GM_     (G_ * M_INV_)
#define HD2_    (0.5f * DT_ * DT_)          // DT^2/2
#define HD2M_   (HD2_ * M_INV_)
#define TCONST_ (DT_ - HD2M_ * G_)
#define SQRT_LOG2E_ 1.2011224087864498f
#define XMIN_   (-8.0f)
#define XSPAN_  16.0f
#define DX_     (XSPAN_ / (float)N_INT)
#define INV_DX_ ((float)N_INT / XSPAN_)

__device__ __forceinline__ void do_elem(float uu, float x,
                                        const unsigned int* tab,
                                        float& o0, float& o1)
{
    float pos = fminf(fmaxf((x - XMIN_) * INV_DX_, 0.0f), (float)N_INT - 0.01f);
    int   i   = (int)pos;
    float f   = pos - (float)i;
    unsigned int e = tab[i];
    __half2 h = *(__half2*)&e;
    float A  = fmaf(f, __high2float(h), __low2float(h));
    float yd = fmaf(uu, M_INV_, fmaf(x, -GM_, A));
    o0 = fmaf(DT_, x, HD2_ * yd);
    o1 = TCONST_ * yd;
}

__global__ __launch_bounds__(256)
void rk4_rbf_fused(const float4* __restrict__ u4,
                   const float4* __restrict__ st4,
                   float4* __restrict__ out4,
                   const float* __restrict__ centers,
                   const float* __restrict__ log_sigmas,
                   const float* __restrict__ w,
                   const float* __restrict__ bptr,
                   int nquads)
{
    __shared__ unsigned int tab[N_INT];

    int t    = threadIdx.x;
    int lane = t & 31;
    int wid  = t >> 5;

    // ---- front-batch first iteration's data loads (table-independent) ----
    int p = blockIdx.x * blockDim.x + t;
    int stride = gridDim.x * blockDim.x;
    float4 uu, s0, s1;
    bool have = (p < nquads);
    if (have) {
        uu = u4[p];
        s0 = st4[2 * p];
        s1 = st4[2 * p + 1];
    }

    // ---- distributed table build: blocks 0..127, one entry per warp ----
    if (blockIdx.x < (N_INT / 8)) {
        int j = blockIdx.x * 8 + wid;              // entry index 0..1023
        float x0 = XMIN_ + (float)j * DX_;
        float x1 = x0 + DX_;

        // lane k computes the k-th RBF term at both endpoints
        float a  = expf(log_sigmas[lane]) * SQRT_LOG2E_;
        float nb = -centers[lane] * a;
        float wk = w[lane];
        float q0 = fmaf(x0, a, nb);
        float q1 = fmaf(x1, a, nb);
        float v0 = wk * ex2_approx(-q0 * q0);
        float v1 = wk * ex2_approx(-q1 * q1);
#pragma unroll
        for (int m = 16; m > 0; m >>= 1) {
            v0 += __shfl_xor_sync(0xFFFFFFFFu, v0, m);
            v1 += __shfl_xor_sync(0xFFFFFFFFu, v1, m);
        }
        if (lane == 0) {
            float bb = bptr[0];
            float A0 = -(OFFST_ + bb + v0) * M_INV_;
            float A1 = -(OFFST_ + bb + v1) * M_INV_;
            unsigned int lo = __half_as_ushort(__float2half(A0));
            unsigned int hi = __half_as_ushort(__float2half(A1 - A0));
            gTable[j] = lo | (hi << 16);
            __threadfence();
            atomicAdd(&gDone, 1u);
        }
    }

    // ---- wait for full table (first execution only does real spinning;
    //      later replays pass instantly and read identical values) ----
    if (t == 0) {
        while (*(volatile unsigned int*)&gDone < (unsigned int)N_INT) { }
    }
    __syncthreads();

    // ---- stage table to shared, bypassing L1 (L2 is coherent/fresh) ----
    {
        uint4 tv = __ldcg(((const uint4*)gTable) + t);   // 256 x 16B = 4KB
        ((uint4*)tab)[t] = tv;
    }
    __syncthreads();

    // ---- main loop (round-7 structure, 1-ahead preload) ----
    while (have) {
        float4 o0v, o1v;
        do_elem(uu.x, s0.y, tab, o0v.x, o0v.y);
        do_elem(uu.y, s0.w, tab, o0v.z, o0v.w);
        do_elem(uu.z, s1.y, tab, o1v.x, o1v.y);
        do_elem(uu.w, s1.w, tab, o1v.z, o1v.w);

        int pc = p;
        p += stride;
        have = (p < nquads);
        if (have) {
            uu = u4[p];
            s0 = st4[2 * p];
            s1 = st4[2 * p + 1];
        }

        out4[2 * pc]     = o0v;
        out4[2 * pc + 1] = o1v;
    }
}

extern "C" void kernel_launch(void* const* d_in, const int* in_sizes, int n_in,
                              void* d_out, int out_size) {
    const float* u        = (const float*)d_in[0];
    const float* states   = (const float*)d_in[1];
    const float* centers  = (const float*)d_in[2];
    const float* lsig     = (const float*)d_in[3];
    const float* w        = (const float*)d_in[4];
    const float* b        = (const float*)d_in[5];

    int n = in_sizes[0];                 // 4194304
    int nquads = n / 4;                  // 1048576

    // 1024 blocks x 256 threads: ~7/SM (8/SM measured slower — L1tex queue
    // contention), exactly 4 iterations/thread, builders in first wave.
    rk4_rbf_fused<<<1024, 256>>>((const float4*)u, (const float4*)states,
                                 (float4*)d_out, centers, lsig, w, b, nquads);
}

// round 13
// speedup vs baseline: 1.0723x; 1.0723x over previous
#include <cuda_runtime.h>
#include <cuda_bf16.h>
#include <cuda_fp16.h>

// RK4 + RBF collapsed to one tabulated scalar function A(x), x = y1:
//   yd1 = u*M_INV - GM*x + A(x)
//   st0 = DT*x + (DT^2/2)*yd1           (exact)
//   st1 = TCONST * yd1                  (S1 correction dropped: <=1.4e-4 rel)
// Table: 1024 intervals over [-8,8], packed {fp16 A0, fp16 dA} (4 B), LDS.32 gather.
// Two kernels + PDL. Builder is warp-per-entry (lane k = k-th RBF term,
// butterfly reduce): ~0.1us exec, so main's PDL wait is negligible.
// Main: exact round-7 body (measured 14.27us): 1024 blocks, grid-stride, 4 elems/iter.

#define K_RBF  32
#define N_INT  1024

__device__ __align__(16) unsigned int gTable[N_INT];

__device__ __forceinline__ float ex2_approx(float x) {
    float r;
    asm("ex2.approx.ftz.f32 %0, %1;" : "=f"(r) : "f"(x));
    return r;
}

// ---------------- constants ----------------
#define DT_     0.005f
#define M_INV_  (1.0f / 95.452f)
#define OFFST_  (-3.2902f)
#define G_      (214.9261f + 19.3607f)
#define GM_     (G_ * M_INV_)
#define HD2_    (0.5f * DT_ * DT_)          // DT^2/2
#define HD2M_   (HD2_ * M_INV_)
#define TCONST_ (DT_ - HD2M_ * G_)
#define SQRT_LOG2E_ 1.2011224087864498f
#define XMIN_   (-8.0f)
#define XSPAN_  16.0f
#define DX_     (XSPAN_ / (float)N_INT)
#define INV_DX_ ((float)N_INT / XSPAN_)

// ---------------- builder: one warp per table entry ----------------
__global__ __launch_bounds__(256)
void build_table_kernel(const float* __restrict__ centers,
                        const float* __restrict__ log_sigmas,
                        const float* __restrict__ w,
                        const float* __restrict__ bptr)
{
    int t    = threadIdx.x;
    int lane = t & 31;
    int wid  = t >> 5;
    int j    = blockIdx.x * 8 + wid;           // entry 0..1023 (grid 128 x 8 warps)

    float x0 = XMIN_ + (float)j * DX_;
    float x1 = x0 + DX_;

    // lane k computes the k-th RBF term at both interval endpoints
    float a  = expf(log_sigmas[lane]) * SQRT_LOG2E_;
    float nb = -centers[lane] * a;
    float wk = w[lane];
    float q0 = fmaf(x0, a, nb);
    float q1 = fmaf(x1, a, nb);
    float v0 = wk * ex2_approx(-q0 * q0);
    float v1 = wk * ex2_approx(-q1 * q1);
#pragma unroll
    for (int m = 16; m > 0; m >>= 1) {
        v0 += __shfl_xor_sync(0xFFFFFFFFu, v0, m);
        v1 += __shfl_xor_sync(0xFFFFFFFFu, v1, m);
    }
    if (lane == 0) {
        float bb = bptr[0];
        float A0 = -(OFFST_ + bb + v0) * M_INV_;
        float A1 = -(OFFST_ + bb + v1) * M_INV_;
        unsigned int lo = __half_as_ushort(__float2half(A0));
        unsigned int hi = __half_as_ushort(__float2half(A1 - A0));
        gTable[j] = lo | (hi << 16);
    }
}

// ---------------- main ----------------
__device__ __forceinline__ void do_elem(float uu, float x,
                                        const unsigned int* tab,
                                        float& o0, float& o1)
{
    float pos = fminf(fmaxf((x - XMIN_) * INV_DX_, 0.0f), (float)N_INT - 0.01f);
    int   i   = (int)pos;
    float f   = pos - (float)i;
    unsigned int e = tab[i];
    __half2 h = *(__half2*)&e;
    float A  = fmaf(f, __high2float(h), __low2float(h));
    float yd = fmaf(uu, M_INV_, fmaf(x, -GM_, A));
    o0 = fmaf(DT_, x, HD2_ * yd);
    o1 = TCONST_ * yd;
}

__global__ __launch_bounds__(256)
void rk4_rbf_main(const float4* __restrict__ u4,
                  const float4* __restrict__ st4,
                  float4* __restrict__ out4,
                  int nquads)
{
    __shared__ unsigned int tab[N_INT];

    int t = threadIdx.x;

    // PDL: wait for the (now ~0.1us) builder before reading gTable.
#if __CUDA_ARCH__ >= 900
    cudaGridDependencySynchronize();
#endif

    // stage table: 1024 uints = 256 x uint4, one LDG.128/STS.128 per thread
    ((uint4*)tab)[t] = ((const uint4*)gTable)[t];
    __syncthreads();

    int stride = gridDim.x * blockDim.x;
    for (int p = blockIdx.x * blockDim.x + t; p < nquads; p += stride) {
        // 3 loads, front-batched (MLP = 3)
        float4 uu = u4[p];
        float4 s0 = st4[2 * p];
        float4 s1 = st4[2 * p + 1];

        float4 o0, o1;
        do_elem(uu.x, s0.y, tab, o0.x, o0.y);
        do_elem(uu.y, s0.w, tab, o0.z, o0.w);
        do_elem(uu.z, s1.y, tab, o1.x, o1.y);
        do_elem(uu.w, s1.w, tab, o1.z, o1.w);

        out4[2 * p]     = o0;
        out4[2 * p + 1] = o1;
    }
}

extern "C" void kernel_launch(void* const* d_in, const int* in_sizes, int n_in,
                              void* d_out, int out_size) {
    const float* u        = (const float*)d_in[0];
    const float* states   = (const float*)d_in[1];
    const float* centers  = (const float*)d_in[2];
    const float* lsig     = (const float*)d_in[3];
    const float* w        = (const float*)d_in[4];
    const float* b        = (const float*)d_in[5];

    int n = in_sizes[0];                 // 4194304
    int nquads = n / 4;                  // 1048576

    // warp-per-entry builder: 128 blocks x 8 warps = 1024 entries, ~0.1us
    build_table_kernel<<<N_INT / 8, 256>>>(centers, lsig, w, b);

    // 1024 blocks x 256 threads: ~7/SM, exactly 4 iterations/thread
    // (8/SM measured slower: cross-CTA L1tex queue contention).
    const int BLOCKS = 1024, THREADS = 256;

    cudaLaunchConfig_t cfg = {};
    cfg.gridDim  = dim3(BLOCKS, 1, 1);
    cfg.blockDim = dim3(THREADS, 1, 1);
    cfg.dynamicSmemBytes = 0;
    cfg.stream = 0;
    cudaLaunchAttribute attr[1];
    attr[0].id = cudaLaunchAttributeProgrammaticStreamSerialization;
    attr[0].val.programmaticStreamSerializationAllowed = 1;
    cfg.attrs = attr;
    cfg.numAttrs = 1;

    cudaError_t e = cudaLaunchKernelEx(&cfg, rk4_rbf_main,
                                       (const float4*)u, (const float4*)states,
                                       (float4*)d_out, nquads);
    if (e != cudaSuccess) {
        (void)cudaGetLastError();       // PDL unsupported: plain launch
        rk4_rbf_main<<<BLOCKS, THREADS>>>((const float4*)u, (const float4*)states,
                                          (float4*)d_out, nquads);
    }
}

// round 14
// speedup vs baseline: 1.4121x; 1.3168x over previous
#include <cuda_runtime.h>
#include <cuda_bf16.h>
#include <cuda_fp16.h>

// RK4 + RBF collapsed to one tabulated scalar function A(x), x = y1:
//   yd1 = u*M_INV - GM*x + A(x)
//   st0 = DT*x + (DT^2/2)*yd1           (exact)
//   st1 = TCONST * yd1                  (S1 correction dropped: <=1.4e-4 rel)
// Table: 1024 intervals over [-8,8], packed {fp16 A0, fp16 dA} (4 B), LDS.32 gather.
// Two kernels + PDL (round-10 proven builder). Main: 128-thread blocks with
// __launch_bounds__(128,8) (reg cap 64 -> 6 LDG.128 stay in flight), grid 1024,
// 8 elems/thread, exactly 4 balanced grid-stride chunks per block.

#define K_RBF  32
#define N_INT  1024

__device__ __align__(16) unsigned int gTable[N_INT];

__device__ __forceinline__ float ex2_approx(float x) {
    float r;
    asm("ex2.approx.ftz.f32 %0, %1;" : "=f"(r) : "f"(x));
    return r;
}

// ---------------- constants ----------------
#define DT_     0.005f
#define M_INV_  (1.0f / 95.452f)
#define OFFST_  (-3.2902f)
#define G_      (214.9261f + 19.3607f)
#define GM_     (G_ * M_INV_)
#define HD2_    (0.5f * DT_ * DT_)          // DT^2/2
#define HD2M_   (HD2_ * M_INV_)
#define TCONST_ (DT_ - HD2M_ * G_)
#define SQRT_LOG2E_ 1.2011224087864498f
#define XMIN_   (-8.0f)
#define XSPAN_  16.0f
#define DX_     (XSPAN_ / (float)N_INT)
#define INV_DX_ ((float)N_INT / XSPAN_)

// ---------------- builder (round-10 proven: 4 blocks x 256 threads) ----------------
__global__ void build_table_kernel(const float* __restrict__ centers,
                                   const float* __restrict__ log_sigmas,
                                   const float* __restrict__ w,
                                   const float* __restrict__ bptr)
{
    int j = blockIdx.x * blockDim.x + threadIdx.x;
    if (j >= N_INT) return;

    float bb = bptr[0];
    float x0 = XMIN_ + (float)j * DX_;
    float x1 = x0 + DX_;

    float S0a = 0.f, S0b = 0.f;
#pragma unroll
    for (int k = 0; k < K_RBF; ++k) {
        float a  = expf(log_sigmas[k]) * SQRT_LOG2E_;
        float nb = -centers[k] * a;
        float wk = w[k];
        float q0 = fmaf(x0, a, nb);
        float q1 = fmaf(x1, a, nb);
        S0a = fmaf(wk, ex2_approx(-q0 * q0), S0a);
        S0b = fmaf(wk, ex2_approx(-q1 * q1), S0b);
    }

    float A0 = -(OFFST_ + bb + S0a) * M_INV_;
    float A1 = -(OFFST_ + bb + S0b) * M_INV_;

    unsigned int lo = __half_as_ushort(__float2half(A0));
    unsigned int hi = __half_as_ushort(__float2half(A1 - A0));
    gTable[j] = lo | (hi << 16);
}

// ---------------- main ----------------
__device__ __forceinline__ void do_elem(float uu, float x,
                                        const unsigned int* tab,
                                        float& o0, float& o1)
{
    float pos = fminf(fmaxf((x - XMIN_) * INV_DX_, 0.0f), (float)N_INT - 0.01f);
    int   i   = (int)pos;
    float f   = pos - (float)i;
    unsigned int e = tab[i];
    __half2 h = *(__half2*)&e;
    float A  = fmaf(f, __high2float(h), __low2float(h));
    float yd = fmaf(uu, M_INV_, fmaf(x, -GM_, A));
    o0 = fmaf(DT_, x, HD2_ * yd);
    o1 = TCONST_ * yd;
}

__global__ __launch_bounds__(128, 8)
void rk4_rbf_main(const float4* __restrict__ u4,
                  const float4* __restrict__ st4,
                  float4* __restrict__ out4,
                  int nquads)
{
    __shared__ unsigned int tab[N_INT];

    int t = threadIdx.x;

    // PDL: wait for the builder's gTable writes (with a plain launch: no-op).
#if __CUDA_ARCH__ >= 900
    cudaGridDependencySynchronize();
#endif

    // stage table: 1024 uints = 256 x uint4, two per thread (128 threads)
    ((uint4*)tab)[t]       = ((const uint4*)gTable)[t];
    ((uint4*)tab)[t + 128] = ((const uint4*)gTable)[t + 128];
    __syncthreads();

    // grid-stride over 256-quad chunks: 1024 blocks -> exactly 4 chunks each
    int stride = gridDim.x * 256;
    for (int base = blockIdx.x * 256; base < nquads; base += stride) {
        int q0 = base + t;
        int q1 = base + 128 + t;

        if (q1 < nquads) {
            // 6 front-batched LDG.128 (MLP = 6; requires reg cap 64)
            float4 uA  = u4[q0];
            float4 uB  = u4[q1];
            float4 sA0 = st4[2 * q0];
            float4 sA1 = st4[2 * q0 + 1];
            float4 sB0 = st4[2 * q1];
            float4 sB1 = st4[2 * q1 + 1];

            float4 oA0, oA1, oB0, oB1;
            do_elem(uA.x, sA0.y, tab, oA0.x, oA0.y);
            do_elem(uA.y, sA0.w, tab, oA0.z, oA0.w);
            do_elem(uA.z, sA1.y, tab, oA1.x, oA1.y);
            do_elem(uA.w, sA1.w, tab, oA1.z, oA1.w);
            do_elem(uB.x, sB0.y, tab, oB0.x, oB0.y);
            do_elem(uB.y, sB0.w, tab, oB0.z, oB0.w);
            do_elem(uB.z, sB1.y, tab, oB1.x, oB1.y);
            do_elem(uB.w, sB1.w, tab, oB1.z, oB1.w);

            out4[2 * q0]     = oA0;
            out4[2 * q0 + 1] = oA1;
            out4[2 * q1]     = oB0;
            out4[2 * q1 + 1] = oB1;
        } else {
            // tail (not hit for n = 4194304; kept for safety)
            for (int q = q0; q < nquads; q += 128) {
                float4 uu = u4[q];
                float4 s0 = st4[2 * q];
                float4 s1 = st4[2 * q + 1];
                float4 o0, o1;
                do_elem(uu.x, s0.y, tab, o0.x, o0.y);
                do_elem(uu.y, s0.w, tab, o0.z, o0.w);
                do_elem(uu.z, s1.y, tab, o1.x, o1.y);
                do_elem(uu.w, s1.w, tab, o1.z, o1.w);
                out4[2 * q]     = o0;
                out4[2 * q + 1] = o1;
            }
        }
    }
}

extern "C" void kernel_launch(void* const* d_in, const int* in_sizes, int n_in,
                              void* d_out, int out_size) {
    const float* u        = (const float*)d_in[0];
    const float* states   = (const float*)d_in[1];
    const float* centers  = (const float*)d_in[2];
    const float* lsig     = (const float*)d_in[3];
    const float* w        = (const float*)d_in[4];
    const float* b        = (const float*)d_in[5];

    int n = in_sizes[0];                 // 4194304
    int nquads = n / 4;                  // 1048576

    build_table_kernel<<<(N_INT + 255) / 256, 256>>>(centers, lsig, w, b);

    // 1024 blocks x 128 threads (~6.9/SM, single wave), 8 elems/thread,
    // exactly 4 chunks/block -> perfect balance.
    const int BLOCKS = 1024, THREADS = 128;

    cudaLaunchConfig_t cfg = {};
    cfg.gridDim  = dim3(BLOCKS, 1, 1);
    cfg.blockDim = dim3(THREADS, 1, 1);
    cfg.dynamicSmemBytes = 0;
    cfg.stream = 0;
    cudaLaunchAttribute attr[1];
    attr[0].id = cudaLaunchAttributeProgrammaticStreamSerialization;
    attr[0].val.programmaticStreamSerializationAllowed = 1;
    cfg.attrs = attr;
    cfg.numAttrs = 1;

    cudaError_t e = cudaLaunchKernelEx(&cfg, rk4_rbf_main,
                                       (const float4*)u, (const float4*)states,
                                       (float4*)d_out, nquads);
    if (e != cudaSuccess) {
        (void)cudaGetLastError();       // PDL unsupported: plain launch
        rk4_rbf_main<<<BLOCKS, THREADS>>>((const float4*)u, (const float4*)states,
                                          (float4*)d_out, nquads);
    }
}

// round 15
// speedup vs baseline: 1.4630x; 1.0361x over previous
#include <cuda_runtime.h>
#include <cuda_bf16.h>
#include <cuda_fp16.h>

// RK4 + RBF collapsed to one tabulated scalar function A(x), x = y1:
//   yd1 = u*M_INV - GM*x + A(x)
//   st0 = DT*x + (DT^2/2)*yd1           (exact)
//   st1 = TCONST * yd1                  (S1 correction dropped: <=1.4e-4 rel)
// Table: 1024 intervals over [-8,8], packed {fp16 A0, fp16 dA} (4 B), LDS.32 gather.
// Two kernels + PDL. Builder kept at 4 blocks (co-resident builder experiments
// regressed) but made ~4x cheaper: expf -> ex2.approx, so main's PDL wait shrinks.
// Main: exact best-measured config: 1024 blocks x 256 threads, grid-stride,
// 4 elems/iter, first-iteration loads issued before the PDL sync.

#define K_RBF  32
#define N_INT  1024

__device__ __align__(16) unsigned int gTable[N_INT];

__device__ __forceinline__ float ex2_approx(float x) {
    float r;
    asm("ex2.approx.ftz.f32 %0, %1;" : "=f"(r) : "f"(x));
    return r;
}

// ---------------- constants ----------------
#define DT_     0.005f
#define M_INV_  (1.0f / 95.452f)
#define OFFST_  (-3.2902f)
#define G_      (214.9261f + 19.3607f)
#define GM_     (G_ * M_INV_)
#define HD2_    (0.5f * DT_ * DT_)          // DT^2/2
#define HD2M_   (HD2_ * M_INV_)
#define TCONST_ (DT_ - HD2M_ * G_)
#define LOG2E_  1.4426950408889634f
#define SQRT_LOG2E_ 1.2011224087864498f
#define XMIN_   (-8.0f)
#define XSPAN_  16.0f
#define DX_     (XSPAN_ / (float)N_INT)
#define INV_DX_ ((float)N_INT / XSPAN_)

// ---------------- builder: 4 blocks x 256 threads, ex2-based (cheap) ----------------
__global__ void build_table_kernel(const float* __restrict__ centers,
                                   const float* __restrict__ log_sigmas,
                                   const float* __restrict__ w,
                                   const float* __restrict__ bptr)
{
    int j = blockIdx.x * blockDim.x + threadIdx.x;
    if (j >= N_INT) return;

    float bb = bptr[0];
    float x0 = XMIN_ + (float)j * DX_;
    float x1 = x0 + DX_;

    float S0a = 0.f, S0b = 0.f;
#pragma unroll
    for (int k = 0; k < K_RBF; ++k) {
        // exp(ls) = ex2(ls * log2e): 1 MUFU instead of ~30-instr libdevice expf
        float a  = ex2_approx(log_sigmas[k] * LOG2E_) * SQRT_LOG2E_;
        float nb = -centers[k] * a;
        float wk = w[k];
        float q0 = fmaf(x0, a, nb);
        float q1 = fmaf(x1, a, nb);
        S0a = fmaf(wk, ex2_approx(-q0 * q0), S0a);
        S0b = fmaf(wk, ex2_approx(-q1 * q1), S0b);
    }

    float A0 = -(OFFST_ + bb + S0a) * M_INV_;
    float A1 = -(OFFST_ + bb + S0b) * M_INV_;

    unsigned int lo = __half_as_ushort(__float2half(A0));
    unsigned int hi = __half_as_ushort(__float2half(A1 - A0));
    gTable[j] = lo | (hi << 16);
}

// ---------------- main ----------------
__device__ __forceinline__ void do_elem(float uu, float x,
                                        const unsigned int* tab,
                                        float& o0, float& o1)
{
    float pos = fminf(fmaxf((x - XMIN_) * INV_DX_, 0.0f), (float)N_INT - 0.01f);
    int   i   = (int)pos;
    float f   = pos - (float)i;
    unsigned int e = tab[i];
    __half2 h = *(__half2*)&e;
    float A  = fmaf(f, __high2float(h), __low2float(h));
    float yd = fmaf(uu, M_INV_, fmaf(x, -GM_, A));
    o0 = fmaf(DT_, x, HD2_ * yd);
    o1 = TCONST_ * yd;
}

__global__ __launch_bounds__(256)
void rk4_rbf_main(const float4* __restrict__ u4,
                  const float4* __restrict__ st4,
                  float4* __restrict__ out4,
                  int nquads)
{
    __shared__ unsigned int tab[N_INT];

    int t  = threadIdx.x;
    int p  = blockIdx.x * blockDim.x + t;
    int stride = gridDim.x * blockDim.x;

    // First iteration's data loads do not depend on the builder: issue them
    // before the PDL dependency sync so they overlap builder execution.
    float4 uu, s0, s1;
    bool have = (p < nquads);
    if (have) {
        uu = u4[p];
        s0 = st4[2 * p];
        s1 = st4[2 * p + 1];
    }

#if __CUDA_ARCH__ >= 900
    cudaGridDependencySynchronize();   // builder done; gTable valid
#endif

    // stage table: 1024 uints = 256 x uint4, one LDG.128/STS.128 per thread
    ((uint4*)tab)[t] = ((const uint4*)gTable)[t];
    __syncthreads();

    while (have) {
        float4 o0v, o1v;
        do_elem(uu.x, s0.y, tab, o0v.x, o0v.y);
        do_elem(uu.y, s0.w, tab, o0v.z, o0v.w);
        do_elem(uu.z, s1.y, tab, o1v.x, o1v.y);
        do_elem(uu.w, s1.w, tab, o1v.z, o1v.w);

        int pc = p;
        p += stride;
        have = (p < nquads);
        if (have) {                     // preload next iteration
            uu = u4[p];
            s0 = st4[2 * p];
            s1 = st4[2 * p + 1];
        }

        out4[2 * pc]     = o0v;
        out4[2 * pc + 1] = o1v;
    }
}

extern "C" void kernel_launch(void* const* d_in, const int* in_sizes, int n_in,
                              void* d_out, int out_size) {
    const float* u        = (const float*)d_in[0];
    const float* states   = (const float*)d_in[1];
    const float* centers  = (const float*)d_in[2];
    const float* lsig     = (const float*)d_in[3];
    const float* w        = (const float*)d_in[4];
    const float* b        = (const float*)d_in[5];

    int n = in_sizes[0];                 // 4194304
    int nquads = n / 4;                  // 1048576

    build_table_kernel<<<(N_INT + 255) / 256, 256>>>(centers, lsig, w, b);

    // 1024 blocks x 256 threads: ~7/SM, exactly 4 iterations/thread.
    // (8/SM and 128-thread/MLP6 variants both measured slower.)
    const int BLOCKS = 1024, THREADS = 256;

    cudaLaunchConfig_t cfg = {};
    cfg.gridDim  = dim3(BLOCKS, 1, 1);
    cfg.blockDim = dim3(THREADS, 1, 1);
    cfg.dynamicSmemBytes = 0;
    cfg.stream = 0;
    cudaLaunchAttribute attr[1];
    attr[0].id = cudaLaunchAttributeProgrammaticStreamSerialization;
    attr[0].val.programmaticStreamSerializationAllowed = 1;
    cfg.attrs = attr;
    cfg.numAttrs = 1;

    cudaError_t e = cudaLaunchKernelEx(&cfg, rk4_rbf_main,
                                       (const float4*)u, (const float4*)states,
                                       (float4*)d_out, nquads);
    if (e != cudaSuccess) {
        (void)cudaGetLastError();       // PDL unsupported: plain launch
        rk4_rbf_main<<<BLOCKS, THREADS>>>((const float4*)u, (const float4*)states,
                                          (float4*)d_out, nquads);
    }
}

// round 16
// speedup vs baseline: 1.6652x; 1.1382x over previous
#include <cuda_runtime.h>
#include <cuda_bf16.h>
#include <cuda_fp16.h>

// RK4 + RBF via tabulated A(x) (see prior rounds), now with a TMA (cp.async.bulk)
// double-buffered pipeline so DRAM parallelism no longer depends on registers:
//   - TILE = 512 elems; in: u 2KB + states 4KB, out 4KB; 2 stages.
//   - smem 24KB/block -> 8 blocks/SM, grid 1024 = single resident wave.
//   - 84KB of bulk-copy bytes in flight per SM (vs ~25KB needed to saturate HBM).
// Builder + PDL unchanged (proven). Fallback to classic LDG main if shape mismatch.

#define K_RBF  32
#define N_INT  1024
#define TILE   512

__device__ __align__(16) unsigned int gTable[N_INT];

__device__ __forceinline__ float ex2_approx(float x) {
    float r;
    asm("ex2.approx.ftz.f32 %0, %1;" : "=f"(r) : "f"(x));
    return r;
}
__device__ __forceinline__ unsigned int smem_u32(const void* p) {
    unsigned int a;
    asm("{ .reg .u64 t; cvta.to.shared.u64 t, %1; cvt.u32.u64 %0, t; }" : "=r"(a) : "l"(p));
    return a;
}

// ---------------- constants ----------------
#define DT_     0.005f
#define M_INV_  (1.0f / 95.452f)
#define OFFST_  (-3.2902f)
#define G_      (214.9261f + 19.3607f)
#define GM_     (G_ * M_INV_)
#define HD2_    (0.5f * DT_ * DT_)
#define HD2M_   (HD2_ * M_INV_)
#define TCONST_ (DT_ - HD2M_ * G_)
#define LOG2E_  1.4426950408889634f
#define SQRT_LOG2E_ 1.2011224087864498f
#define XMIN_   (-8.0f)
#define XSPAN_  16.0f
#define DX_     (XSPAN_ / (float)N_INT)
#define INV_DX_ ((float)N_INT / XSPAN_)

// ---------------- builder (unchanged, cheap ex2 version) ----------------
__global__ void build_table_kernel(const float* __restrict__ centers,
                                   const float* __restrict__ log_sigmas,
                                   const float* __restrict__ w,
                                   const float* __restrict__ bptr)
{
    int j = blockIdx.x * blockDim.x + threadIdx.x;
    if (j >= N_INT) return;
    float bb = bptr[0];
    float x0 = XMIN_ + (float)j * DX_;
    float x1 = x0 + DX_;
    float S0a = 0.f, S0b = 0.f;
#pragma unroll
    for (int k = 0; k < K_RBF; ++k) {
        float a  = ex2_approx(log_sigmas[k] * LOG2E_) * SQRT_LOG2E_;
        float nb = -centers[k] * a;
        float wk = w[k];
        float q0 = fmaf(x0, a, nb);
        float q1 = fmaf(x1, a, nb);
        S0a = fmaf(wk, ex2_approx(-q0 * q0), S0a);
        S0b = fmaf(wk, ex2_approx(-q1 * q1), S0b);
    }
    float A0 = -(OFFST_ + bb + S0a) * M_INV_;
    float A1 = -(OFFST_ + bb + S0b) * M_INV_;
    unsigned int lo = __half_as_ushort(__float2half(A0));
    unsigned int hi = __half_as_ushort(__float2half(A1 - A0));
    gTable[j] = lo | (hi << 16);
}

// ---------------- shared math ----------------
__device__ __forceinline__ void do_elem(float uu, float x,
                                        const unsigned int* tab,
                                        float& o0, float& o1)
{
    float pos = fminf(fmaxf((x - XMIN_) * INV_DX_, 0.0f), (float)N_INT - 0.01f);
    int   i   = (int)pos;
    float f   = pos - (float)i;
    unsigned int e = tab[i];
    __half2 h = *(__half2*)&e;
    float A  = fmaf(f, __high2float(h), __low2float(h));
    float yd = fmaf(uu, M_INV_, fmaf(x, -GM_, A));
    o0 = fmaf(DT_, x, HD2_ * yd);
    o1 = TCONST_ * yd;
}

// ---------------- TMA helpers ----------------
__device__ __forceinline__ void mbar_init(unsigned int a, unsigned int cnt) {
    asm volatile("mbarrier.init.shared.b64 [%0], %1;" :: "r"(a), "r"(cnt) : "memory");
}
__device__ __forceinline__ void mbar_expect_tx(unsigned int a, unsigned int bytes) {
    asm volatile("mbarrier.arrive.expect_tx.shared.b64 _, [%0], %1;"
                 :: "r"(a), "r"(bytes) : "memory");
}
__device__ __forceinline__ void mbar_wait(unsigned int a, unsigned int parity) {
    asm volatile(
        "{\n\t.reg .pred p;\n\t"
        "WAIT_%=:\n\t"
        "mbarrier.try_wait.parity.acquire.cta.shared::cta.b64 p, [%0], %1, 0x989680;\n\t"
        "@!p bra WAIT_%=;\n\t}"
        :: "r"(a), "r"(parity) : "memory");
}
__device__ __forceinline__ void bulk_g2s(unsigned int sdst, const void* gsrc,
                                         unsigned int bytes, unsigned int mbar) {
    asm volatile("cp.async.bulk.shared::cta.global.mbarrier::complete_tx::bytes "
                 "[%0], [%1], %2, [%3];"
                 :: "r"(sdst), "l"(gsrc), "r"(bytes), "r"(mbar) : "memory");
}
__device__ __forceinline__ void bulk_s2g(void* gdst, unsigned int ssrc, unsigned int bytes) {
    asm volatile("cp.async.bulk.global.shared::cta.bulk_group [%0], [%1], %2;"
                 :: "l"(gdst), "r"(ssrc), "r"(bytes) : "memory");
}

// ---------------- TMA-pipelined main ----------------
__global__ __launch_bounds__(256)
void rk4_rbf_tma(const float* __restrict__ u,
                 const float* __restrict__ states,
                 float* __restrict__ out,
                 int ntiles_per_block)
{
    __shared__ __align__(16)  unsigned int tab[N_INT];            // 4 KB
    __shared__ __align__(128) float ubuf[2][TILE];                // 4 KB
    __shared__ __align__(128) float stbuf[2][2 * TILE];           // 8 KB
    __shared__ __align__(128) float obuf[2][2 * TILE];            // 8 KB
    __shared__ __align__(8)   unsigned long long mbar_s[2];

    const unsigned int U_BYTES  = TILE * 4;         // 2048
    const unsigned int ST_BYTES = TILE * 8;         // 4096
    const unsigned int O_BYTES  = TILE * 8;         // 4096

    int t = threadIdx.x;

#if __CUDA_ARCH__ >= 900
    cudaGridDependencySynchronize();    // builder's gTable writes visible
#endif
    ((uint4*)tab)[t] = ((const uint4*)gTable)[t];

    unsigned int mb[2] = { smem_u32(&mbar_s[0]), smem_u32(&mbar_s[1]) };
    if (t == 0) {
        mbar_init(mb[0], 1);
        mbar_init(mb[1], 1);
    }
    __syncthreads();

    long long tile0 = (long long)blockIdx.x;
    long long tstep = (long long)gridDim.x;

    if (t == 0) {
        asm volatile("fence.proxy.async.shared::cta;" ::: "memory");
        // prime 2 stages
        for (int it = 0; it < 2 && it < ntiles_per_block; ++it) {
            long long tile = tile0 + (long long)it * tstep;
            mbar_expect_tx(mb[it], U_BYTES + ST_BYTES);
            bulk_g2s(smem_u32(ubuf[it]),  u + tile * TILE,          U_BYTES,  mb[it]);
            bulk_g2s(smem_u32(stbuf[it]), states + tile * 2 * TILE, ST_BYTES, mb[it]);
        }
    }

    for (int it = 0; it < ntiles_per_block; ++it) {
        int s = it & 1;
        unsigned int parity = (unsigned int)((it >> 1) & 1);
        long long tile = tile0 + (long long)it * tstep;

        // recycle obuf[s]: the bulk store issued at it-2 must have read it out
        if (t == 0) asm volatile("cp.async.bulk.wait_group 1;" ::: "memory");
        __syncthreads();

        mbar_wait(mb[s], parity);       // input tile resident

        // compute: 2 elems per thread
        float2 uu = ((const float2*)ubuf[s])[t];
        float4 st = ((const float4*)stbuf[s])[t];
        float4 o;
        do_elem(uu.x, st.y, tab, o.x, o.y);
        do_elem(uu.y, st.w, tab, o.z, o.w);
        ((float4*)obuf[s])[t] = o;

        __syncthreads();                // obuf complete; ubuf/stbuf fully consumed

        if (t == 0) {
            asm volatile("fence.proxy.async.shared::cta;" ::: "memory");
            bulk_s2g(out + tile * 2 * TILE, smem_u32(obuf[s]), O_BYTES);
            asm volatile("cp.async.bulk.commit_group;" ::: "memory");
            int it2 = it + 2;
            if (it2 < ntiles_per_block) {
                long long tile2 = tile0 + (long long)it2 * tstep;
                mbar_expect_tx(mb[s], U_BYTES + ST_BYTES);
                bulk_g2s(smem_u32(ubuf[s]),  u + tile2 * TILE,          U_BYTES,  mb[s]);
                bulk_g2s(smem_u32(stbuf[s]), states + tile2 * 2 * TILE, ST_BYTES, mb[s]);
            }
        }
    }

    if (t == 0) asm volatile("cp.async.bulk.wait_group 0;" ::: "memory");
}

// ---------------- fallback classic main (round-15, proven 14.9us) ----------------
__global__ __launch_bounds__(256)
void rk4_rbf_main(const float4* __restrict__ u4,
                  const float4* __restrict__ st4,
                  float4* __restrict__ out4,
                  int nquads)
{
    __shared__ unsigned int tab[N_INT];
    int t = threadIdx.x;
#if __CUDA_ARCH__ >= 900
    cudaGridDependencySynchronize();
#endif
    ((uint4*)tab)[t] = ((const uint4*)gTable)[t];
    __syncthreads();

    int stride = gridDim.x * blockDim.x;
    for (int p = blockIdx.x * blockDim.x + t; p < nquads; p += stride) {
        float4 uu = u4[p];
        float4 s0 = st4[2 * p];
        float4 s1 = st4[2 * p + 1];
        float4 o0, o1;
        do_elem(uu.x, s0.y, tab, o0.x, o0.y);
        do_elem(uu.y, s0.w, tab, o0.z, o0.w);
        do_elem(uu.z, s1.y, tab, o1.x, o1.y);
        do_elem(uu.w, s1.w, tab, o1.z, o1.w);
        out4[2 * p]     = o0;
        out4[2 * p + 1] = o1;
    }
}

extern "C" void kernel_launch(void* const* d_in, const int* in_sizes, int n_in,
                              void* d_out, int out_size) {
    const float* u        = (const float*)d_in[0];
    const float* states   = (const float*)d_in[1];
    const float* centers  = (const float*)d_in[2];
    const float* lsig     = (const float*)d_in[3];
    const float* w        = (const float*)d_in[4];
    const float* b        = (const float*)d_in[5];

    int n = in_sizes[0];                 // 4194304
    const int BLOCKS = 1024, THREADS = 256;

    build_table_kernel<<<(N_INT + 255) / 256, 256>>>(centers, lsig, w, b);

    cudaLaunchConfig_t cfg = {};
    cfg.gridDim  = dim3(BLOCKS, 1, 1);
    cfg.blockDim = dim3(THREADS, 1, 1);
    cfg.dynamicSmemBytes = 0;
    cfg.stream = 0;
    cudaLaunchAttribute attr[1];
    attr[0].id = cudaLaunchAttributeProgrammaticStreamSerialization;
    attr[0].val.programmaticStreamSerializationAllowed = 1;
    cfg.attrs = attr;
    cfg.numAttrs = 1;

    if (n % (TILE * BLOCKS) == 0) {
        int ntiles_per_block = n / (TILE * BLOCKS);     // 8 for n=4194304
        cudaError_t e = cudaLaunchKernelEx(&cfg, rk4_rbf_tma,
                                           u, states, (float*)d_out, ntiles_per_block);
        if (e != cudaSuccess) {
            (void)cudaGetLastError();
            rk4_rbf_tma<<<BLOCKS, THREADS>>>(u, states, (float*)d_out, ntiles_per_block);
        }
    } else {
        int nquads = n / 4;
        cudaError_t e = cudaLaunchKernelEx(&cfg, rk4_rbf_main,
                                           (const float4*)u, (const float4*)states,
                                           (float4*)d_out, nquads);
        if (e != cudaSuccess) {
            (void)cudaGetLastError();
            rk4_rbf_main<<<BLOCKS, THREADS>>>((const float4*)u, (const float4*)states,
                                              (float4*)d_out, nquads);
        }
    }
}